// round 12
// baseline (speedup 1.0000x reference)
#include <cuda_runtime.h>
#include <cuda_bf16.h>

// ---------------------------------------------------------------------------
// VQC: 4 qubits, 3 layers, BATCH=524288.
// z_w(x) = exact 81-term polynomial in {1, cos x_q, sin x_q}^{⊗4};
// coefficients T (81 x float4) depend only on weights.
// Kernel 1 (1 block, 8 warps): BARRIER-FREE shuffle builder — each lane owns
//   one amplitude of one U column (warp = 2 columns); CNOT = shfl gather,
//   RY = shfl.bfly + 4 FMA, RZ = diagonal. Then M_w = Re(U^† S_w U) -> T.
// Kernel 2 (EPT=2, TPB=128, 7 CTAs/SM; PDL): nested contraction
//   z = Σ_gi g_gi Σ_i2 v2[i2] Σ_i3 T[gi,i2,i3] v3[i3]   (packed fma.rn.f32x2).
// ---------------------------------------------------------------------------

#define DIM 16

__device__ float4 g_T[81];

// ---------------- packed f32x2 helpers (PTX-only on Blackwell) -------------
__device__ __forceinline__ unsigned long long pack2(float lo, float hi) {
    unsigned long long r;
    asm("mov.b64 %0, {%1, %2};" : "=l"(r) : "f"(lo), "f"(hi));
    return r;
}
__device__ __forceinline__ void unpack2(unsigned long long v, float& lo, float& hi) {
    asm("mov.b64 {%0, %1}, %2;" : "=f"(lo), "=f"(hi) : "l"(v));
}
__device__ __forceinline__ unsigned long long fma2(unsigned long long a,
                                                   unsigned long long b,
                                                   unsigned long long c) {
    unsigned long long d;
    asm("fma.rn.f32x2 %0, %1, %2, %3;" : "=l"(d) : "l"(a), "l"(b), "l"(c));
    return d;
}
__device__ __forceinline__ unsigned long long mul2(unsigned long long a,
                                                   unsigned long long b) {
    unsigned long long d;
    asm("mul.rn.f32x2 %0, %1, %2;" : "=l"(d) : "l"(a), "l"(b));
    return d;
}

// CNOT ring permutation for one layer (gather index).
__device__ __forceinline__ int cnot_q(int idx) {
    int q = idx;
#pragma unroll
    for (int i = 3; i >= 0; --i)
        q = q ^ ((((q >> (3 - i)) & 1)) << (3 - ((i + 1) & 3)));
    return q;
}

// ---------------- Kernel 1: weights -> polynomial coefficients T -----------
__global__ void vqc_build_T(const float* __restrict__ w) {
    __shared__ float2 sU[DIM * 17];   // sU[col*17 + amp]
    __shared__ float4 sM[256];

    const int t = threadIdx.x;
    const int lane = t & 31;
    const int wi = t >> 5;
    const unsigned FULL = 0xffffffffu;

    // ---- Phase A: shuffle-circuit U builder (no __syncthreads inside) ----
    // gate params held in lanes 0..11 (lane = layer*4 + wire)
    float my_cy, my_sy, my_cz, my_sz;
    {
        const float wy = (lane < 12) ? w[lane * 2 + 0] : 0.f;
        const float wz = (lane < 12) ? w[lane * 2 + 1] : 0.f;
        __sincosf(0.5f * wy, &my_sy, &my_cy);
        __sincosf(0.5f * wz, &my_sz, &my_cz);
    }
    // lane = (colHalf, amp): warp wi owns columns 2wi, 2wi+1
    const int amp = lane & 15;
    const int col = (wi << 1) | (lane >> 4);
    float re = (amp == col) ? 1.f : 0.f;
    float im = 0.f;

#pragma unroll
    for (int layer = 0; layer < 3; ++layer) {
        // CNOT ring: new[amp] = old[Q(amp)] — shfl gather within 16-lane half
        {
            const int srcLane = (lane & 16) | cnot_q(amp);
            const float nre = __shfl_sync(FULL, re, srcLane);
            const float nim = __shfl_sync(FULL, im, srcLane);
            re = nre; im = nim;
        }
#pragma unroll
        for (int g = 0; g < 4; ++g) {
            const int gidx = layer * 4 + g;
            const float cy = __shfl_sync(FULL, my_cy, gidx);
            const float sy = __shfl_sync(FULL, my_sy, gidx);
            const int bit = 3 - g, mask = 1 << bit;
            const float pre = __shfl_xor_sync(FULL, re, mask);
            const float pim = __shfl_xor_sync(FULL, im, mask);
            // RY: b0 = cy a0 - sy a1 ; b1 = sy a0 + cy a1
            float br, bi;
            if (amp & mask) { br = sy * pre + cy * re; bi = sy * pim + cy * im; }
            else            { br = cy * re - sy * pre; bi = cy * im - sy * pim; }
            re = br; im = bi;
            if (layer != 2) {   // RZ (last layer's RZ cancels in U^H S U)
                const float cz = __shfl_sync(FULL, my_cz, gidx);
                const float sz = __shfl_sync(FULL, my_sz, gidx);
                if (amp & mask) { const float o = cz * br - sz * bi;
                                  im = cz * bi + sz * br; re = o; }
                else            { const float o = cz * br + sz * bi;
                                  im = cz * bi - sz * br; re = o; }
            }
        }
    }
    sU[col * 17 + amp] = make_float2(re, im);
    __syncthreads();

    // ---- Phase M: M_w[j,j'] = sum_k s_wk (Ur Ur' + Ui Ui') ----------------
    {
        const int j = t >> 4, jp = t & 15;
        float m0 = 0.f, m1 = 0.f, m2 = 0.f, m3 = 0.f;
#pragma unroll
        for (int k = 0; k < DIM; ++k) {
            const float2 a = sU[j * 17 + k];
            const float2 b = sU[jp * 17 + k];
            const float pr = a.x * b.x + a.y * b.y;
            if (k & 8) m0 -= pr; else m0 += pr;
            if (k & 4) m1 -= pr; else m1 += pr;
            if (k & 2) m2 -= pr; else m2 += pr;
            if (k & 1) m3 -= pr; else m3 += pr;
        }
        sM[t] = make_float4(m0, m1, m2, m3);   // t = j*16 + jp
    }
    __syncthreads();

    // ---- Phase T -> global, then PDL trigger ------------------------------
    if (t < 81) {
        const int i0 = t / 27, i1 = (t / 9) % 3, i2 = (t / 3) % 3, i3 = t % 3;
        const int M1 = ((i0 == 1) << 3) | ((i1 == 1) << 2) | ((i2 == 1) << 1) | (i3 == 1);
        const int M2 = ((i0 == 2) << 3) | ((i1 == 2) << 2) | ((i2 == 2) << 1) | (i3 == 2);
        float a0 = 0.f, a1 = 0.f, a2 = 0.f, a3 = 0.f;
#pragma unroll
        for (int b = 0; b < 16; ++b) {
            const float4 mm = sM[b * 16 + (b ^ M2)];
            const float sg = (__popc(b & M1) & 1) ? -1.f : 1.f;
            a0 += sg * mm.x; a1 += sg * mm.y; a2 += sg * mm.z; a3 += sg * mm.w;
        }
        const float s = 0.0625f;
        g_T[t] = make_float4(a0 * s, a1 * s, a2 * s, a3 * s);
        __threadfence();
    }
    __syncthreads();
    cudaTriggerProgrammaticLaunchCompletion();
}

// ---------------- Kernel 2: batched polynomial evaluation ------------------
#define TPB 128
#define EPT 2
#define TILE (TPB * EPT)

__global__ __launch_bounds__(TPB, 7)
void vqc_poly_apply(const float* __restrict__ x, float* __restrict__ out, int B) {
    __shared__ float4 sT[81];
    const int t = threadIdx.x;
    const int base = blockIdx.x * TILE + t;

    // ---- builder-independent preamble (overlaps PDL wait) ----
    bool valid[EPT];
    unsigned long long c0d[EPT], s0d[EPT], c1d[EPT], s1d[EPT];
    unsigned long long c2d[EPT], s2d[EPT], c3d[EPT], s3d[EPT];
#pragma unroll
    for (int e = 0; e < EPT; ++e) {
        const int b = base + e * TPB;
        valid[e] = (b < B);
        const float4 xv = valid[e] ? reinterpret_cast<const float4*>(x)[b]
                                   : make_float4(0.f, 0.f, 0.f, 0.f);
        float c0, s0, c1, s1, c2, s2, c3, s3;
        __sincosf(xv.x, &s0, &c0);   // full angle (double-angle folded into T)
        __sincosf(xv.y, &s1, &c1);
        __sincosf(xv.z, &s2, &c2);
        __sincosf(xv.w, &s3, &c3);
        c0d[e] = pack2(c0, c0); s0d[e] = pack2(s0, s0);
        c1d[e] = pack2(c1, c1); s1d[e] = pack2(s1, s1);
        c2d[e] = pack2(c2, c2); s2d[e] = pack2(s2, s2);
        c3d[e] = pack2(c3, c3); s3d[e] = pack2(s3, s3);
    }

    // ---- wait for builder, stage T into smem ----
    cudaGridDependencySynchronize();
    if (t < 81) sT[t] = g_T[t];
    __syncthreads();

    unsigned long long z01[EPT], z23[EPT];
    const ulonglong2* cT = reinterpret_cast<const ulonglong2*>(sT);

#pragma unroll
    for (int gi = 0; gi < 9; ++gi) {
        unsigned long long in01[EPT], in23[EPT];
        // nested (i2,(i3)) contraction: 3 coeff-pairs live at a time
#pragma unroll
        for (int i2 = 0; i2 < 3; ++i2) {
            const ulonglong2 ca = cT[gi * 9 + i2 * 3 + 0];
            const ulonglong2 cb = cT[gi * 9 + i2 * 3 + 1];
            const ulonglong2 cc = cT[gi * 9 + i2 * 3 + 2];
#pragma unroll
            for (int e = 0; e < EPT; ++e) {
                const unsigned long long u01 =
                    fma2(cc.x, s3d[e], fma2(cb.x, c3d[e], ca.x));
                const unsigned long long u23 =
                    fma2(cc.y, s3d[e], fma2(cb.y, c3d[e], ca.y));
                if (i2 == 0)      { in01[e] = u01;                        in23[e] = u23; }
                else if (i2 == 1) { in01[e] = fma2(u01, c2d[e], in01[e]); in23[e] = fma2(u23, c2d[e], in23[e]); }
                else              { in01[e] = fma2(u01, s2d[e], in01[e]); in23[e] = fma2(u23, s2d[e], in23[e]); }
            }
        }
        // accumulate with g_gi over (q0,q1); g_0 = 1
#pragma unroll
        for (int e = 0; e < EPT; ++e) {
            switch (gi) {
                case 0: z01[e] = in01[e];                       z23[e] = in23[e];                       break;
                case 1: z01[e] = fma2(c1d[e], in01[e], z01[e]); z23[e] = fma2(c1d[e], in23[e], z23[e]); break;
                case 2: z01[e] = fma2(s1d[e], in01[e], z01[e]); z23[e] = fma2(s1d[e], in23[e], z23[e]); break;
                case 3: z01[e] = fma2(c0d[e], in01[e], z01[e]); z23[e] = fma2(c0d[e], in23[e], z23[e]); break;
                case 4: { const unsigned long long g = mul2(c0d[e], c1d[e]);
                          z01[e] = fma2(g, in01[e], z01[e]);    z23[e] = fma2(g, in23[e], z23[e]); }    break;
                case 5: { const unsigned long long g = mul2(c0d[e], s1d[e]);
                          z01[e] = fma2(g, in01[e], z01[e]);    z23[e] = fma2(g, in23[e], z23[e]); }    break;
                case 6: z01[e] = fma2(s0d[e], in01[e], z01[e]); z23[e] = fma2(s0d[e], in23[e], z23[e]); break;
                case 7: { const unsigned long long g = mul2(s0d[e], c1d[e]);
                          z01[e] = fma2(g, in01[e], z01[e]);    z23[e] = fma2(g, in23[e], z23[e]); }    break;
                case 8: { const unsigned long long g = mul2(s0d[e], s1d[e]);
                          z01[e] = fma2(g, in01[e], z01[e]);    z23[e] = fma2(g, in23[e], z23[e]); }    break;
            }
        }
    }

#pragma unroll
    for (int e = 0; e < EPT; ++e) {
        if (!valid[e]) continue;
        float z0, z1, z2, z3;
        unpack2(z01[e], z0, z1);
        unpack2(z23[e], z2, z3);
        reinterpret_cast<float4*>(out)[base + e * TPB] = make_float4(z0, z1, z2, z3);
    }
}

// ---------------------------------------------------------------------------
extern "C" void kernel_launch(void* const* d_in, const int* in_sizes, int n_in,
                              void* d_out, int out_size) {
    int ix = 0, iw = 1;
    if (n_in >= 2 && in_sizes[0] <= in_sizes[1]) { ix = 1; iw = 0; }
    const float* x = (const float*)d_in[ix];
    const float* w = (const float*)d_in[iw];
    float* out = (float*)d_out;
    const int B = in_sizes[ix] / 4;

    vqc_build_T<<<1, 256>>>(w);

    const int grid = (B + TILE - 1) / TILE;
    cudaLaunchConfig_t cfg = {};
    cfg.gridDim = dim3(grid, 1, 1);
    cfg.blockDim = dim3(TPB, 1, 1);
    cudaLaunchAttribute attr[1];
    attr[0].id = cudaLaunchAttributeProgrammaticStreamSerialization;
    attr[0].val.programmaticStreamSerializationAllowed = 1;
    cfg.attrs = attr;
    cfg.numAttrs = 1;
    cudaLaunchKernelEx(&cfg, vqc_poly_apply, x, out, B);
}

// round 13
// speedup vs baseline: 1.1379x; 1.1379x over previous
#include <cuda_runtime.h>
#include <cuda_bf16.h>

// ---------------------------------------------------------------------------
// VQC: 4 qubits, 3 layers, BATCH=524288.
// z_w(x) = exact 81-term polynomial in {1, cos x_q, sin x_q}^{⊗4};
// coefficients T (81 x float4) depend only on weights.
// Kernel 1 (1 block, smem builder — R10-proven): U -> M_w -> T.
// Kernel 2 (EPT=2, TPB=128, 6 CTAs/SM; PDL): three-level Horner
//   z = Σ_i0 v0[i0] Σ_i1 v1[i1] Σ_i2 v2[i2] Σ_i3 T[i0,i1,i2,i3] v3[i3]
// packed fma.rn.f32x2 lanes = (w0,w1)/(w2,w3); 9 coeffs batch-loaded per group.
// ---------------------------------------------------------------------------

#define DIM 16

__device__ float4 g_T[81];

// ---------------- packed f32x2 helpers (PTX-only on Blackwell) -------------
__device__ __forceinline__ unsigned long long pack2(float lo, float hi) {
    unsigned long long r;
    asm("mov.b64 %0, {%1, %2};" : "=l"(r) : "f"(lo), "f"(hi));
    return r;
}
__device__ __forceinline__ void unpack2(unsigned long long v, float& lo, float& hi) {
    asm("mov.b64 {%0, %1}, %2;" : "=f"(lo), "=f"(hi) : "l"(v));
}
__device__ __forceinline__ unsigned long long fma2(unsigned long long a,
                                                   unsigned long long b,
                                                   unsigned long long c) {
    unsigned long long d;
    asm("fma.rn.f32x2 %0, %1, %2, %3;" : "=l"(d) : "l"(a), "l"(b), "l"(c));
    return d;
}

// CNOT ring permutation for one layer (gather index).
__device__ __forceinline__ int cnot_q(int idx) {
    int q = idx;
#pragma unroll
    for (int i = 3; i >= 0; --i)
        q = q ^ ((((q >> (3 - i)) & 1)) << (3 - ((i + 1) & 3)));
    return q;
}

// ---------------- Kernel 1: weights -> polynomial coefficients T -----------
__global__ void vqc_build_T(const float* __restrict__ w) {
    __shared__ float2 sState[DIM * 17];
    __shared__ float4 sGate[12];
    __shared__ float4 sM[256];

    const int t = threadIdx.x;

    if (t < 12) {
        float cy, sy, cz, sz;
        __sincosf(0.5f * w[t * 2 + 0], &sy, &cy);
        __sincosf(0.5f * w[t * 2 + 1], &sz, &cz);
        sGate[t] = make_float4(cy, sy, cz, sz);
    }
    {
        const int col = t >> 4, amp = t & 15;
        sState[col * 17 + amp] = make_float2((amp == col) ? 1.0f : 0.0f, 0.0f);
    }
    __syncthreads();

#pragma unroll
    for (int layer = 0; layer < 3; ++layer) {
        {   // CNOT ring stage
            const int col = t >> 4, idx = t & 15;
            const float2 v = sState[col * 17 + cnot_q(idx)];
            __syncthreads();
            sState[col * 17 + idx] = v;
            __syncthreads();
        }
#pragma unroll
        for (int g = 0; g < 4; ++g) {
            if (t < 128) {
                const int bit = 3 - g, mask = 1 << bit;
                const int col = t >> 3, pair = t & 7;
                const int i0 = ((pair >> bit) << (bit + 1)) | (pair & (mask - 1));
                const int i1 = i0 | mask;
                const float4 gp = sGate[layer * 4 + g];
                const float cy = gp.x, sy = gp.y;
                const float2 a0 = sState[col * 17 + i0];
                const float2 a1 = sState[col * 17 + i1];
                float b0r = cy * a0.x - sy * a1.x, b0i = cy * a0.y - sy * a1.y;
                float b1r = sy * a0.x + cy * a1.x, b1i = sy * a0.y + cy * a1.y;
                if (layer != 2) {   // last-layer RZ cancels in U^H S U
                    const float cz = gp.z, sz = gp.w;
                    const float o0r = cz * b0r + sz * b0i, o0i = cz * b0i - sz * b0r;
                    const float o1r = cz * b1r - sz * b1i, o1i = cz * b1i + sz * b1r;
                    b0r = o0r; b0i = o0i; b1r = o1r; b1i = o1i;
                }
                sState[col * 17 + i0] = make_float2(b0r, b0i);
                sState[col * 17 + i1] = make_float2(b1r, b1i);
            }
            __syncthreads();
        }
    }

    // Phase M: M_w[j,j'] = sum_k s_wk (Ur Ur' + Ui Ui')
    {
        const int j = t >> 4, jp = t & 15;
        float m0 = 0.f, m1 = 0.f, m2 = 0.f, m3 = 0.f;
#pragma unroll
        for (int k = 0; k < DIM; ++k) {
            const float2 a = sState[j * 17 + k];
            const float2 b = sState[jp * 17 + k];
            const float pr = a.x * b.x + a.y * b.y;
            if (k & 8) m0 -= pr; else m0 += pr;
            if (k & 4) m1 -= pr; else m1 += pr;
            if (k & 2) m2 -= pr; else m2 += pr;
            if (k & 1) m3 -= pr; else m3 += pr;
        }
        sM[t] = make_float4(m0, m1, m2, m3);
    }
    __syncthreads();

    // Phase T -> global, then PDL trigger
    if (t < 81) {
        const int i0 = t / 27, i1 = (t / 9) % 3, i2 = (t / 3) % 3, i3 = t % 3;
        const int M1 = ((i0 == 1) << 3) | ((i1 == 1) << 2) | ((i2 == 1) << 1) | (i3 == 1);
        const int M2 = ((i0 == 2) << 3) | ((i1 == 2) << 2) | ((i2 == 2) << 1) | (i3 == 2);
        float a0 = 0.f, a1 = 0.f, a2 = 0.f, a3 = 0.f;
#pragma unroll
        for (int b = 0; b < 16; ++b) {
            const float4 mm = sM[b * 16 + (b ^ M2)];
            const float sg = (__popc(b & M1) & 1) ? -1.f : 1.f;
            a0 += sg * mm.x; a1 += sg * mm.y; a2 += sg * mm.z; a3 += sg * mm.w;
        }
        const float s = 0.0625f;
        g_T[t] = make_float4(a0 * s, a1 * s, a2 * s, a3 * s);
        __threadfence();
    }
    __syncthreads();
    cudaTriggerProgrammaticLaunchCompletion();
}

// ---------------- Kernel 2: batched polynomial evaluation ------------------
#define TPB 128
#define EPT 2
#define TILE (TPB * EPT)

__global__ __launch_bounds__(TPB, 6)
void vqc_poly_apply(const float* __restrict__ x, float* __restrict__ out, int B) {
    __shared__ float4 sT[81];
    const int t = threadIdx.x;
    const int base = blockIdx.x * TILE + t;

    // ---- builder-independent preamble (overlaps PDL wait) ----
    bool valid[EPT];
    unsigned long long c0d[EPT], s0d[EPT], c1d[EPT], s1d[EPT];
    unsigned long long c2d[EPT], s2d[EPT], c3d[EPT], s3d[EPT];
#pragma unroll
    for (int e = 0; e < EPT; ++e) {
        const int b = base + e * TPB;
        valid[e] = (b < B);
        const float4 xv = valid[e] ? reinterpret_cast<const float4*>(x)[b]
                                   : make_float4(0.f, 0.f, 0.f, 0.f);
        float c0, s0, c1, s1, c2, s2, c3, s3;
        __sincosf(xv.x, &s0, &c0);   // full angle (double-angle folded into T)
        __sincosf(xv.y, &s1, &c1);
        __sincosf(xv.z, &s2, &c2);
        __sincosf(xv.w, &s3, &c3);
        c0d[e] = pack2(c0, c0); s0d[e] = pack2(s0, s0);
        c1d[e] = pack2(c1, c1); s1d[e] = pack2(s1, s1);
        c2d[e] = pack2(c2, c2); s2d[e] = pack2(s2, s2);
        c3d[e] = pack2(c3, c3); s3d[e] = pack2(s3, s3);
    }

    // ---- wait for builder, stage T into smem ----
    cudaGridDependencySynchronize();
    if (t < 81) sT[t] = g_T[t];
    __syncthreads();

    unsigned long long z01[EPT], z23[EPT];   // three-level Horner accumulators
    unsigned long long Q01[EPT], Q23[EPT];
    const ulonglong2* cT = reinterpret_cast<const ulonglong2*>(sT);

#pragma unroll
    for (int i0 = 0; i0 < 3; ++i0) {
#pragma unroll
        for (int i1 = 0; i1 < 3; ++i1) {
            const int gi = i0 * 3 + i1;
            // batch-load the 9 coefficient float4s of this group (MLP)
            ulonglong2 c[9];
#pragma unroll
            for (int k = 0; k < 9; ++k) c[k] = cT[gi * 9 + k];

#pragma unroll
            for (int e = 0; e < EPT; ++e) {
                // u_i2 = T[..,i2,0] + c3*T[..,i2,1] + s3*T[..,i2,2] (independent)
                const unsigned long long u0a =
                    fma2(c[2].x, s3d[e], fma2(c[1].x, c3d[e], c[0].x));
                const unsigned long long u1a =
                    fma2(c[5].x, s3d[e], fma2(c[4].x, c3d[e], c[3].x));
                const unsigned long long u2a =
                    fma2(c[8].x, s3d[e], fma2(c[7].x, c3d[e], c[6].x));
                const unsigned long long in01 =
                    fma2(u2a, s2d[e], fma2(u1a, c2d[e], u0a));
                const unsigned long long u0b =
                    fma2(c[2].y, s3d[e], fma2(c[1].y, c3d[e], c[0].y));
                const unsigned long long u1b =
                    fma2(c[5].y, s3d[e], fma2(c[4].y, c3d[e], c[3].y));
                const unsigned long long u2b =
                    fma2(c[8].y, s3d[e], fma2(c[7].y, c3d[e], c[6].y));
                const unsigned long long in23 =
                    fma2(u2b, s2d[e], fma2(u1b, c2d[e], u0b));

                // fold into Q (over i1: v1 = {1, c1, s1})
                if (i1 == 0)      { Q01[e] = in01;                        Q23[e] = in23; }
                else if (i1 == 1) { Q01[e] = fma2(c1d[e], in01, Q01[e]);  Q23[e] = fma2(c1d[e], in23, Q23[e]); }
                else              { Q01[e] = fma2(s1d[e], in01, Q01[e]);  Q23[e] = fma2(s1d[e], in23, Q23[e]); }
            }
        }
        // fold group into z (over i0: v0 = {1, c0, s0})
#pragma unroll
        for (int e = 0; e < EPT; ++e) {
            if (i0 == 0)      { z01[e] = Q01[e];                        z23[e] = Q23[e]; }
            else if (i0 == 1) { z01[e] = fma2(c0d[e], Q01[e], z01[e]);  z23[e] = fma2(c0d[e], Q23[e], z23[e]); }
            else              { z01[e] = fma2(s0d[e], Q01[e], z01[e]);  z23[e] = fma2(s0d[e], Q23[e], z23[e]); }
        }
    }

#pragma unroll
    for (int e = 0; e < EPT; ++e) {
        if (!valid[e]) continue;
        float z0, z1, z2, z3;
        unpack2(z01[e], z0, z1);
        unpack2(z23[e], z2, z3);
        reinterpret_cast<float4*>(out)[base + e * TPB] = make_float4(z0, z1, z2, z3);
    }
}

// ---------------------------------------------------------------------------
extern "C" void kernel_launch(void* const* d_in, const int* in_sizes, int n_in,
                              void* d_out, int out_size) {
    int ix = 0, iw = 1;
    if (n_in >= 2 && in_sizes[0] <= in_sizes[1]) { ix = 1; iw = 0; }
    const float* x = (const float*)d_in[ix];
    const float* w = (const float*)d_in[iw];
    float* out = (float*)d_out;
    const int B = in_sizes[ix] / 4;

    vqc_build_T<<<1, 256>>>(w);

    const int grid = (B + TILE - 1) / TILE;
    cudaLaunchConfig_t cfg = {};
    cfg.gridDim = dim3(grid, 1, 1);
    cfg.blockDim = dim3(TPB, 1, 1);
    cudaLaunchAttribute attr[1];
    attr[0].id = cudaLaunchAttributeProgrammaticStreamSerialization;
    attr[0].val.programmaticStreamSerializationAllowed = 1;
    cfg.attrs = attr;
    cfg.numAttrs = 1;
    cudaLaunchKernelEx(&cfg, vqc_poly_apply, x, out, B);
}